// round 16
// baseline (speedup 1.0000x reference)
#include <cuda_runtime.h>
#include <cuda_fp16.h>
#include <cstdint>

// ChannelAttentionModule: out = x + (F @ softmax(F^T F)^T), F = x.reshape(B,C,N)
// B=8, C=64, N=4096. One-hot-aware flash attention.
// R16: screening GEMM in int8 (m16n8k32.s8 -> 16 IMMA/tile vs 32 HMMA),
// S for the ~2 non-skipped tiles from the same s32 accumulators (/256).
// GEMM2 (P@V + ones row-sums) unchanged in fp16.

constexpr int C    = 64;
constexpr int NPOS = 4096;
constexpr int NB   = 8;
constexpr int BM   = 128;
constexpr int BN   = 64;
constexpr int NT   = NPOS / BN;    // 64
constexpr int LDKB = 144;          // fp16 K row: 128B data + 16B pad
constexpr int LDK8 = 80;           // s8 row: 64B data + 16B pad
constexpr int LDO  = 68;

__device__ __half g_cn[(size_t)NB * C * NPOS];   // fp16 x, [b][c][n]  (V / GEMM2)
__device__ int8_t g_q8[(size_t)NB * NPOS * C];   // s8 16*x, [b][n][c] (screen Q & K)

// ---------------- prepass: fp16 [c][n] + s8 [n][c] in one pass ----------------
__global__ void prep_kernel(const float* __restrict__ x) {
    __shared__ float t[32][33];
    int b = blockIdx.z, cb = blockIdx.y * 32, nb = blockIdx.x * 32;
    int tx = threadIdx.x, ty = threadIdx.y;
    const float* xb = x + (size_t)b * C * NPOS;
    #pragma unroll
    for (int i = 0; i < 4; ++i) {
        int c = cb + ty + 8 * i;
        float v = xb[(size_t)c * NPOS + nb + tx];
        t[ty + 8 * i][tx] = v;
        g_cn[((size_t)b * C + c) * NPOS + nb + tx] = __float2half_rn(v);
    }
    __syncthreads();
    #pragma unroll
    for (int i = 0; i < 4; ++i) {
        float v = t[tx][ty + 8 * i];          // = x[cb+tx][nb+ty+8i]
        int qv = __float2int_rn(16.0f * v);
        qv = max(-127, min(127, qv));
        g_q8[((size_t)b * NPOS + nb + ty + 8 * i) * C + cb + tx] = (int8_t)qv;
    }
}

// ---------------- PTX helpers ----------------
__device__ __forceinline__ uint32_t smem_u32(const void* p) {
    uint32_t a;
    asm("{ .reg .u64 t; cvta.to.shared.u64 t, %1; cvt.u32.u64 %0, t; }" : "=r"(a) : "l"(p));
    return a;
}
__device__ __forceinline__ void cpa16(uint32_t dst, const void* src) {
    asm volatile("cp.async.ca.shared.global [%0], [%1], 16;"
                 :: "r"(dst), "l"(__cvta_generic_to_global(src)));
}
#define CP_COMMIT() asm volatile("cp.async.commit_group;" ::: "memory")
#define CP_WAIT1()  asm volatile("cp.async.wait_group 1;" ::: "memory")

__device__ __forceinline__ void ldsm_x4(uint32_t a, uint32_t& r0, uint32_t& r1,
                                        uint32_t& r2, uint32_t& r3) {
    asm volatile("ldmatrix.sync.aligned.m8n8.x4.shared.b16 {%0,%1,%2,%3}, [%4];"
                 : "=r"(r0), "=r"(r1), "=r"(r2), "=r"(r3) : "r"(a));
}
__device__ __forceinline__ void ldsm_x2(uint32_t a, uint32_t& r0, uint32_t& r1) {
    asm volatile("ldmatrix.sync.aligned.m8n8.x2.shared.b16 {%0,%1}, [%2];"
                 : "=r"(r0), "=r"(r1) : "r"(a));
}
__device__ __forceinline__ void mma16816(float* d, uint32_t a0, uint32_t a1,
                                         uint32_t a2, uint32_t a3,
                                         uint32_t b0, uint32_t b1) {
    asm volatile("mma.sync.aligned.m16n8k16.row.col.f32.f16.f16.f32 "
                 "{%0,%1,%2,%3}, {%4,%5,%6,%7}, {%8,%9}, {%0,%1,%2,%3};"
                 : "+f"(d[0]), "+f"(d[1]), "+f"(d[2]), "+f"(d[3])
                 : "r"(a0), "r"(a1), "r"(a2), "r"(a3), "r"(b0), "r"(b1));
}
__device__ __forceinline__ void imma16832(int* d, uint32_t a0, uint32_t a1,
                                          uint32_t a2, uint32_t a3,
                                          uint32_t b0, uint32_t b1) {
    asm volatile("mma.sync.aligned.m16n8k32.row.col.s32.s8.s8.s32 "
                 "{%0,%1,%2,%3}, {%4,%5,%6,%7}, {%8,%9}, {%0,%1,%2,%3};"
                 : "+r"(d[0]), "+r"(d[1]), "+r"(d[2]), "+r"(d[3])
                 : "r"(a0), "r"(a1), "r"(a2), "r"(a3), "r"(b0), "r"(b1));
}
__device__ __forceinline__ uint32_t packh2(float x, float y) {
    __half2 h = __floats2half2_rn(x, y);
    return *(uint32_t*)&h;
}
__device__ __forceinline__ uint32_t ex2h2(uint32_t a) {
    uint32_t r;
    asm("ex2.approx.f16x2 %0, %1;" : "=r"(r) : "r"(a));
    return r;
}

// ---------------- smem layout (bytes) ----------------
constexpr int SM_Q8   = 0;                        // Q s8 staging [128][80] = 10240
constexpr int SM_KV   = BM * LDK8;                // 10240
constexpr int K8OFF   = 72 * LDKB;                // s8 tile after fp16 data+ones
constexpr int KBUF    = K8OFF + 64 * LDK8;        // 10368 + 5120 = 15488
constexpr int NBUF    = 6;
constexpr int SMEM_BYTES = SM_KV + NBUF * KBUF;   // 103168 -> 2 CTAs/SM

constexpr float L2E     = 1.4426950408889634f;
constexpr float MARGINS = 16.0f;    // screen margin (int8 noise ~0.3, slack 1.5)
constexpr float S256    = 1.0f / 256.0f;

__global__ __launch_bounds__(256, 2)
void attn_mma_kernel(const float* __restrict__ x, float* __restrict__ out)
{
    extern __shared__ char smraw[];
    const uint32_t sb = smem_u32(smraw);

    const int tid  = threadIdx.x;
    const int w    = tid >> 5;
    const int lane = tid & 31;
    const int g    = lane >> 2;
    const int q    = lane & 3;
    const int l16  = lane & 15;
    const int hsel = (lane >> 4) * 16;

    const int b  = blockIdx.y;
    const int m0 = blockIdx.x * BM;
    const int jsel0 = blockIdx.x * 2;             // self tiles first
    const size_t bC = (size_t)b * C;
    const size_t bN = (size_t)b * NPOS;

    // ones rows (c=64..71) of every K buffer's fp16 part
    for (int idx = tid; idx < NBUF * 8 * 9; idx += 256) {
        int buf = idx / 72, rem = idx % 72;
        int r = rem / 9, ch = rem % 9;
        uint32_t a = sb + SM_KV + buf * KBUF + (64 + r) * LDKB + ch * 16;
        const uint32_t one2 = 0x3C003C00u;
        asm volatile("st.shared.v4.b32 [%0], {%1,%1,%1,%1};" :: "r"(a), "r"(one2));
    }

    // helper lambda-ish loads via macros would be nicer; write them out.
    // ---- prologue: group0 = Q8 staging + pair0 (bufs 0,1); group1 = pair1 ----
    #pragma unroll
    for (int it = 0; it < 2; ++it) {
        int idx = tid + it * 256;                 // 512 chunks: 128 rows x 4
        int r = idx >> 2, ch = idx & 3;
        cpa16(sb + SM_Q8 + r * LDK8 + ch * 16, g_q8 + (bN + m0 + r) * C + ch * 16);
    }
    #pragma unroll
    for (int pr = 0; pr < 2; ++pr) {
        #pragma unroll
        for (int u = 0; u < 2; ++u) {
            const int tt = 2 * pr + u;
            const int n0 = ((jsel0 + tt) & (NT - 1)) * BN;
            uint32_t base = sb + SM_KV + tt * KBUF;
            #pragma unroll
            for (int it = 0; it < 2; ++it) {      // fp16 tile: 512 chunks
                int idx = tid + it * 256;
                int r = idx >> 3, ch = idx & 7;
                cpa16(base + r * LDKB + ch * 16, g_cn + (bC + r) * NPOS + n0 + ch * 8);
            }
            {                                      // s8 tile: 256 chunks
                int r = tid >> 2, ch = tid & 3;
                cpa16(base + K8OFF + r * LDK8 + ch * 16,
                      g_q8 + (bN + n0 + r) * C + ch * 16);
            }
        }
        CP_COMMIT();   // one group per pair
    }

    // ---- wait group0, hoist int8 Q fragments ----
    CP_WAIT1();
    __syncthreads();
    uint32_t QI[2][4];
    #pragma unroll
    for (int ks = 0; ks < 2; ++ks)
        ldsm_x4(sb + SM_Q8 + (w * 16 + l16) * LDK8 + hsel + ks * 32,
                QI[ks][0], QI[ks][1], QI[ks][2], QI[ks][3]);

    float M0 = -1e30f, M1 = -1e30f;
    float O[8][4], Ol[4];
    #pragma unroll
    for (int i = 0; i < 8; ++i)
        #pragma unroll
        for (int k = 0; k < 4; ++k) O[i][k] = 0.f;
    #pragma unroll
    for (int k = 0; k < 4; ++k) Ol[k] = 0.f;

    for (int t = 0; t < NT; t += 2) {
        CP_WAIT1();           // pair t/2 resident
        __syncthreads();      // all warps past pair t/2-1

        // prefetch pair t/2+2 (tiles t+4,t+5) -> bufs (2t+4)%6 (pair t/2-1's, free)
        #pragma unroll
        for (int u = 4; u <= 5; ++u) {
            if (t + u < NT) {
                const int n0 = ((jsel0 + t + u) & (NT - 1)) * BN;
                uint32_t base = sb + SM_KV + ((t + u) % NBUF) * KBUF;
                #pragma unroll
                for (int it = 0; it < 2; ++it) {
                    int idx = tid + it * 256;
                    int r = idx >> 3, ch = idx & 7;
                    cpa16(base + r * LDKB + ch * 16,
                          g_cn + (bC + r) * NPOS + n0 + ch * 8);
                }
                {
                    int r = tid >> 2, ch = tid & 3;
                    cpa16(base + K8OFF + r * LDK8 + ch * 16,
                          g_q8 + (bN + n0 + r) * C + ch * 16);
                }
            }
        }
        CP_COMMIT();          // dense group numbering

        #pragma unroll
        for (int u = 0; u < 2; ++u) {
            const uint32_t kvb = sb + SM_KV + ((t + u) % NBUF) * KBUF;
            const uint32_t k8b = kvb + K8OFF;

            // ---- int8 screen: S_int = Qq @ Kq^T  (16 IMMA) ----
            int acc[8][4];
            #pragma unroll
            for (int j = 0; j < 8; ++j)
                #pragma unroll
                for (int k = 0; k < 4; ++k) acc[j][k] = 0;

            const uint32_t k8r = k8b + (l16 & 7) * LDK8 + ((l16 >> 3) << 4);
            #pragma unroll
            for (int ks = 0; ks < 2; ++ks) {
                #pragma unroll
                for (int j = 0; j < 8; ++j) {
                    uint32_t b0, b1;
                    ldsm_x2(k8r + (8 * j) * LDK8 + ks * 32, b0, b1);
                    imma16832(acc[j], QI[ks][0], QI[ks][1], QI[ks][2], QI[ks][3],
                              b0, b1);
                }
            }

            // per-lane integer maxes
            int mi0 = acc[0][0] > acc[0][1] ? acc[0][0] : acc[0][1];
            int mi1 = acc[0][2] > acc[0][3] ? acc[0][2] : acc[0][3];
            #pragma unroll
            for (int j = 1; j < 8; ++j) {
                mi0 = max(mi0, max(acc[j][0], acc[j][1]));
                mi1 = max(mi1, max(acc[j][2], acc[j][3]));
            }
            float mx0 = (float)mi0 * S256;
            float mx1 = (float)mi1 * S256;

            const unsigned vote = __ballot_sync(0xffffffffu,
                (mx0 >= M0 - MARGINS) | (mx1 >= M1 - MARGINS));
            if (vote != 0) {
                mx0 = fmaxf(mx0, __shfl_xor_sync(0xffffffffu, mx0, 1));
                mx0 = fmaxf(mx0, __shfl_xor_sync(0xffffffffu, mx0, 2));
                mx1 = fmaxf(mx1, __shfl_xor_sync(0xffffffffu, mx1, 1));
                mx1 = fmaxf(mx1, __shfl_xor_sync(0xffffffffu, mx1, 2));
                const bool chg = (mx0 > M0) | (mx1 > M1);
                if (__any_sync(0xffffffffu, chg)) {
                    const float nM0 = fmaxf(M0, mx0), nM1 = fmaxf(M1, mx1);
                    const float sc0 = exp2f((M0 - nM0) * L2E);
                    const float sc1 = exp2f((M1 - nM1) * L2E);
                    M0 = nM0; M1 = nM1;
                    #pragma unroll
                    for (int ct = 0; ct < 8; ++ct) {
                        O[ct][0] *= sc0; O[ct][1] *= sc0;
                        O[ct][2] *= sc1; O[ct][3] *= sc1;
                    }
                    Ol[0] *= sc0; Ol[1] *= sc0; Ol[2] *= sc1; Ol[3] *= sc1;
                }

                // P = exp(S - M), S = acc/256 (f32)
                uint32_t P01[8], P23[8];
                #pragma unroll
                for (int j = 0; j < 8; ++j) {
                    float s0 = (float)acc[j][0] * S256;
                    float s1 = (float)acc[j][1] * S256;
                    float s2 = (float)acc[j][2] * S256;
                    float s3 = (float)acc[j][3] * S256;
                    P01[j] = ex2h2(packh2((s0 - M0) * L2E, (s1 - M0) * L2E));
                    P23[j] = ex2h2(packh2((s2 - M1) * L2E, (s3 - M1) * L2E));
                }

                // GEMM2 (fp16): [O | l] += P @ [V | 1]
                #pragma unroll
                for (int kk = 0; kk < 4; ++kk) {
                    const uint32_t a0 = P01[2 * kk],     a1 = P23[2 * kk];
                    const uint32_t a2 = P01[2 * kk + 1], a3 = P23[2 * kk + 1];
                    #pragma unroll
                    for (int ct2 = 0; ct2 < 4; ++ct2) {
                        uint32_t r0, r1, r2, r3;
                        ldsm_x4(kvb + (ct2 * 16 + l16) * LDKB + kk * 32 + hsel,
                                r0, r1, r2, r3);
                        mma16816(O[2 * ct2],     a0, a1, a2, a3, r0, r2);
                        mma16816(O[2 * ct2 + 1], a0, a1, a2, a3, r1, r3);
                    }
                    {
                        uint32_t o0, o1;
                        ldsm_x2(kvb + (64 + (l16 & 7)) * LDKB + kk * 32 +
                                ((l16 >> 3) * 16), o0, o1);
                        mma16816(Ol, a0, a1, a2, a3, o0, o1);
                    }
                }
            }
        }
    }

    __syncthreads();

    // ---- epilogue ----
    float* Sst = (float*)smraw;
    const float i0 = 1.0f / Ol[0], i1 = 1.0f / Ol[2];
    const int r0 = w * 16 + g, r1 = r0 + 8;
    #pragma unroll
    for (int ct = 0; ct < 8; ++ct) {
        Sst[r0 * LDO + 8 * ct + 2 * q]     = O[ct][0] * i0;
        Sst[r0 * LDO + 8 * ct + 2 * q + 1] = O[ct][1] * i0;
        Sst[r1 * LDO + 8 * ct + 2 * q]     = O[ct][2] * i1;
        Sst[r1 * LDO + 8 * ct + 2 * q + 1] = O[ct][3] * i1;
    }
    __syncthreads();

    #pragma unroll
    for (int it = 0; it < 32; ++it) {
        int flat = it * 256 + tid;
        int m = flat & 127, c = flat >> 7;
        const size_t o = (bC + c) * NPOS + m0 + m;
        out[o] = x[o] + Sst[m * LDO + c];
    }
}

extern "C" void kernel_launch(void* const* d_in, const int* in_sizes, int n_in,
                              void* d_out, int out_size)
{
    const float* x = (const float*)d_in[0];
    float* out = (float*)d_out;

    dim3 tg(NPOS / 32, C / 32, NB);
    prep_kernel<<<tg, dim3(32, 8)>>>(x);

    cudaFuncSetAttribute(attn_mma_kernel,
                         cudaFuncAttributeMaxDynamicSharedMemorySize, SMEM_BYTES);
    dim3 grid(NPOS / BM, NB);
    attn_mma_kernel<<<grid, 256, SMEM_BYTES>>>(x, out);
}

// round 17
// speedup vs baseline: 1.2294x; 1.2294x over previous
#include <cuda_runtime.h>
#include <cuda_fp16.h>
#include <cstdint>

// ChannelAttentionModule: out = x + (F @ softmax(F^T F)^T), F = x.reshape(B,C,N)
// B=8, C=64, N=4096. R17: symmetric Gram screening.
// Phase A computes each unordered off-diagonal 128x128 logit block ONCE
// (halving screen HMMAs), accumulating row maxes into g_M (atomicMax) and
// flagging pairs with non-negligible mass. Phase B (fixed M, no online
// rescale) processes self tiles + flagged partners only.

constexpr int C    = 64;
constexpr int NPOS = 4096;
constexpr int NB   = 8;
constexpr int BM   = 128;
constexpr int NBLK = NPOS / BM;    // 32 query blocks
constexpr int NPAIR = NBLK * (NBLK - 1) / 2;  // 496
constexpr int LDKB = 144;          // 64-key tile row: 128B + 16B pad
constexpr int LDQ  = 272;          // 128-col tile row: 256B + 16B pad
constexpr int LDO  = 68;

__device__ __half g_cn[(size_t)NB * C * NPOS];   // fp16 x, [b][c][n]
__device__ float  g_Mest[NB * NPOS];             // self logits (seed / flag ref)
__device__ int    g_M[NB * NPOS];                // running max as float bits
__device__ unsigned g_mask[NB * NBLK];           // flagged partner blocks

constexpr float L2E    = 1.4426950408889634f;
constexpr float MARGIN = 18.0f;

// ---------------- PTX helpers ----------------
__device__ __forceinline__ uint32_t smem_u32(const void* p) {
    uint32_t a;
    asm("{ .reg .u64 t; cvta.to.shared.u64 t, %1; cvt.u32.u64 %0, t; }" : "=r"(a) : "l"(p));
    return a;
}
__device__ __forceinline__ void cpa16(uint32_t dst, const void* src) {
    asm volatile("cp.async.ca.shared.global [%0], [%1], 16;"
                 :: "r"(dst), "l"(__cvta_generic_to_global(src)));
}
#define CP_COMMIT() asm volatile("cp.async.commit_group;" ::: "memory")
#define CP_WAIT0()  asm volatile("cp.async.wait_group 0;" ::: "memory")

__device__ __forceinline__ void ldsm_x4(uint32_t a, uint32_t& r0, uint32_t& r1,
                                        uint32_t& r2, uint32_t& r3) {
    asm volatile("ldmatrix.sync.aligned.m8n8.x4.shared.b16 {%0,%1,%2,%3}, [%4];"
                 : "=r"(r0), "=r"(r1), "=r"(r2), "=r"(r3) : "r"(a));
}
__device__ __forceinline__ void ldsm_x4t(uint32_t a, uint32_t& r0, uint32_t& r1,
                                         uint32_t& r2, uint32_t& r3) {
    asm volatile("ldmatrix.sync.aligned.m8n8.x4.trans.shared.b16 {%0,%1,%2,%3}, [%4];"
                 : "=r"(r0), "=r"(r1), "=r"(r2), "=r"(r3) : "r"(a));
}
__device__ __forceinline__ void ldsm_x2(uint32_t a, uint32_t& r0, uint32_t& r1) {
    asm volatile("ldmatrix.sync.aligned.m8n8.x2.shared.b16 {%0,%1}, [%2];"
                 : "=r"(r0), "=r"(r1) : "r"(a));
}
__device__ __forceinline__ void mma16816(float* d, uint32_t a0, uint32_t a1,
                                         uint32_t a2, uint32_t a3,
                                         uint32_t b0, uint32_t b1) {
    asm volatile("mma.sync.aligned.m16n8k16.row.col.f32.f16.f16.f32 "
                 "{%0,%1,%2,%3}, {%4,%5,%6,%7}, {%8,%9}, {%0,%1,%2,%3};"
                 : "+f"(d[0]), "+f"(d[1]), "+f"(d[2]), "+f"(d[3])
                 : "r"(a0), "r"(a1), "r"(a2), "r"(a3), "r"(b0), "r"(b1));
}
__device__ __forceinline__ void mma16816h(uint32_t& d0, uint32_t& d1,
                                          uint32_t a0, uint32_t a1,
                                          uint32_t a2, uint32_t a3,
                                          uint32_t b0, uint32_t b1) {
    asm volatile("mma.sync.aligned.m16n8k16.row.col.f16.f16.f16.f16 "
                 "{%0,%1}, {%2,%3,%4,%5}, {%6,%7}, {%0,%1};"
                 : "+r"(d0), "+r"(d1)
                 : "r"(a0), "r"(a1), "r"(a2), "r"(a3), "r"(b0), "r"(b1));
}
__device__ __forceinline__ uint32_t packh2(float x, float y) {
    __half2 h = __floats2half2_rn(x, y);
    return *(uint32_t*)&h;
}
__device__ __forceinline__ uint32_t ex2h2(uint32_t a) {
    uint32_t r;
    asm("ex2.approx.f16x2 %0, %1;" : "=r"(r) : "r"(a));
    return r;
}
__device__ __forceinline__ uint32_t h2u(__half2 h) { return *(uint32_t*)&h; }
__device__ __forceinline__ __half2 u2h(uint32_t u) { return *(__half2*)&u; }
__device__ __forceinline__ uint32_t hmax2u(uint32_t a, uint32_t b) {
    return h2u(__hmax2(u2h(a), u2h(b)));
}

// ---------------- prepass: fp16 convert ----------------
__global__ void prep_kernel(const float* __restrict__ x) {
    size_t i = ((size_t)blockIdx.x * 256 + threadIdx.x) * 4;
    float4 v = *(const float4*)(x + i);
    *(__half2*)(g_cn + i)     = __floats2half2_rn(v.x, v.y);
    *(__half2*)(g_cn + i + 2) = __floats2half2_rn(v.z, v.w);
}

// diag: Mest + seed g_M + zero masks  (re-seeded every launch -> graph-safe)
__global__ void diag_kernel() {
    int b = blockIdx.y;
    int n = blockIdx.x * 256 + threadIdx.x;
    const __half* p = g_cn + (size_t)b * C * NPOS + n;
    float s = 0.f;
    #pragma unroll
    for (int c = 0; c < C; ++c) {
        float v = __half2float(p[(size_t)c * NPOS]);
        s = fmaf(v, v, s);
    }
    g_Mest[b * NPOS + n] = s;
    g_M[b * NPOS + n] = __float_as_int(s);       // s >= 0 -> int-atomicMax valid
    if (blockIdx.x == 0 && blockIdx.y == 0 && threadIdx.x < NB * NBLK)
        g_mask[threadIdx.x] = 0u;
}

// ---------------- Phase A: symmetric screen ----------------
constexpr int A_TI   = 0;
constexpr int A_TJ   = A_TI + 64 * LDQ;          // 17408
constexpr int A_SCOL = A_TJ + 64 * LDQ;          // 34816: u32[8][64]
constexpr int A_FLG  = A_SCOL + 8 * 64 * 4;      // 36864: int[2]
constexpr int A_SMEM = A_FLG + 16;

__global__ __launch_bounds__(256, 2)
void screen_kernel()
{
    extern __shared__ char smraw[];
    const uint32_t sb = smem_u32(smraw);
    uint32_t* scol = (uint32_t*)(smraw + A_SCOL);
    int* flg = (int*)(smraw + A_FLG);

    const int tid  = threadIdx.x;
    const int w    = tid >> 5;
    const int lane = tid & 31;
    const int g    = lane >> 2;
    const int q    = lane & 3;
    const int l16  = lane & 15;
    const int hsel = (lane >> 4) * 16;

    const int b = blockIdx.y;
    // decode pair index -> (i, j), i < j
    int i = 0, rem = blockIdx.x;
    while (rem >= NBLK - 1 - i) { rem -= NBLK - 1 - i; ++i; }
    const int j = i + 1 + rem;

    const size_t bC = (size_t)b * C;
    const size_t bN = (size_t)b * NPOS;

    if (tid < 2) flg[tid] = 0;

    // load Fi, Fj tiles [c=64][128 halves]
    #pragma unroll
    for (int it = 0; it < 4; ++it) {
        int idx = tid + it * 256;
        int r = idx >> 4, ch = idx & 15;
        cpa16(sb + A_TI + r * LDQ + ch * 16, g_cn + (bC + r) * NPOS + i * BM + ch * 8);
        cpa16(sb + A_TJ + r * LDQ + ch * 16, g_cn + (bC + r) * NPOS + j * BM + ch * 8);
    }
    CP_COMMIT();
    CP_WAIT0();
    __syncthreads();

    // A fragments (rows of block i, this warp's 16 rows)
    uint32_t QF[4][4];
    #pragma unroll
    for (int k = 0; k < 4; ++k) {
        uint32_t r0, r1, r2, r3;
        ldsm_x4t(sb + A_TI + (k * 16 + l16) * LDQ + w * 32 + hsel, r0, r1, r2, r3);
        QF[k][0] = r0; QF[k][1] = r2; QF[k][2] = r1; QF[k][3] = r3;
    }

    // S block: 16 rows x 128 cols, f16 accum, 64 HMMA
    uint32_t Sc0[16], Sc1[16];
    #pragma unroll
    for (int s = 0; s < 16; ++s) { Sc0[s] = 0u; Sc1[s] = 0u; }

    #pragma unroll
    for (int k = 0; k < 4; ++k) {
        const uint32_t krow = sb + A_TJ + (k * 16 + l16) * LDQ + hsel;
        #pragma unroll
        for (int nt2 = 0; nt2 < 8; ++nt2) {
            uint32_t b0, b1, b2, b3;
            ldsm_x4t(krow + nt2 * 32, b0, b1, b2, b3);
            mma16816h(Sc0[2 * nt2],     Sc1[2 * nt2],
                      QF[k][0], QF[k][1], QF[k][2], QF[k][3], b0, b1);
            mma16816h(Sc0[2 * nt2 + 1], Sc1[2 * nt2 + 1],
                      QF[k][0], QF[k][1], QF[k][2], QF[k][3], b2, b3);
        }
    }

    // ---- row maxes (rows of block i) ----
    uint32_t rlo = Sc0[0], rhi = Sc1[0];
    #pragma unroll
    for (int s = 1; s < 16; ++s) { rlo = hmax2u(rlo, Sc0[s]); rhi = hmax2u(rhi, Sc1[s]); }
    float rm0 = fmaxf(__low2float(u2h(rlo)), __high2float(u2h(rlo)));
    float rm1 = fmaxf(__low2float(u2h(rhi)), __high2float(u2h(rhi)));
    rm0 = fmaxf(rm0, __shfl_xor_sync(0xffffffffu, rm0, 1));
    rm0 = fmaxf(rm0, __shfl_xor_sync(0xffffffffu, rm0, 2));
    rm1 = fmaxf(rm1, __shfl_xor_sync(0xffffffffu, rm1, 1));
    rm1 = fmaxf(rm1, __shfl_xor_sync(0xffffffffu, rm1, 2));

    const int rowg  = i * BM + w * 16 + g;
    if (q == 0) {
        atomicMax(&g_M[bN + rowg],     __float_as_int(rm0));
        atomicMax(&g_M[bN + rowg + 8], __float_as_int(rm1));
    }
    {
        const float me0 = g_Mest[bN + rowg];
        const float me1 = g_Mest[bN + rowg + 8];
        const bool f = (rm0 >= me0 - MARGIN) | (rm1 >= me1 - MARGIN);
        if (__any_sync(0xffffffffu, f) && lane == 0) flg[0] = 1;
    }

    // ---- column maxes (rows of block j) ----
    uint32_t cm[16];
    #pragma unroll
    for (int s = 0; s < 16; ++s) cm[s] = hmax2u(Sc0[s], Sc1[s]);
    #pragma unroll
    for (int mk = 4; mk <= 16; mk <<= 1)
        #pragma unroll
        for (int s = 0; s < 16; ++s)
            cm[s] = hmax2u(cm[s], __shfl_xor_sync(0xffffffffu, cm[s], mk));
    if (lane < 4)
        #pragma unroll
        for (int s = 0; s < 16; ++s)
            scol[w * 64 + s * 4 + lane] = cm[s];
    __syncthreads();

    if (tid < 64) {
        uint32_t v = scol[tid];
        #pragma unroll
        for (int w2 = 1; w2 < 8; ++w2) v = hmax2u(v, scol[w2 * 64 + tid]);
        const int s = tid >> 2, qq = tid & 3;
        const int n = j * BM + s * 8 + 2 * qq;
        const float c0 = __low2float(u2h(v));
        const float c1 = __high2float(u2h(v));
        atomicMax(&g_M[bN + n],     __float_as_int(c0));
        atomicMax(&g_M[bN + n + 1], __float_as_int(c1));
        const float me0 = g_Mest[bN + n], me1 = g_Mest[bN + n + 1];
        if ((c0 >= me0 - MARGIN) | (c1 >= me1 - MARGIN)) flg[1] = 1;
    }
    __syncthreads();
    if (tid == 0) {
        if (flg[0]) atomicOr(&g_mask[b * NBLK + i], 1u << j);
        if (flg[1]) atomicOr(&g_mask[b * NBLK + j], 1u << i);
    }
}

// ---------------- Phase B: fixed-M flash over worklist ----------------
constexpr int B_Q    = 0;                         // [64][LDQ] = 17408
constexpr int B_KV   = 64 * LDQ;
constexpr int KBUF   = 72 * LDKB;                 // 64 data + 8 ones rows
constexpr int B_SMEM = B_KV + 2 * KBUF;           // 38144

__global__ __launch_bounds__(256, 2)
void attn_mma_kernel(const float* __restrict__ x, float* __restrict__ out)
{
    extern __shared__ char smraw[];
    const uint32_t sb = smem_u32(smraw);

    const int tid  = threadIdx.x;
    const int w    = tid >> 5;
    const int lane = tid & 31;
    const int g    = lane >> 2;
    const int q    = lane & 3;
    const int l16  = lane & 15;
    const int hsel = (lane >> 4) * 16;

    const int b  = blockIdx.y;
    const int ib = blockIdx.x;              // query block
    const int m0 = ib * BM;
    const size_t bC = (size_t)b * C;
    const size_t bN = (size_t)b * NPOS;

    // ones rows of both buffers
    for (int idx = tid; idx < 2 * 8 * 9; idx += 256) {
        int buf = idx / 72, rem = idx % 72;
        int r = rem / 9, ch = rem % 9;
        uint32_t a = sb + B_KV + buf * KBUF + (64 + r) * LDKB + ch * 16;
        const uint32_t one2 = 0x3C003C00u;
        asm volatile("st.shared.v4.b32 [%0], {%1,%1,%1,%1};" :: "r"(a), "r"(one2));
    }

    unsigned rem = g_mask[b * NBLK + ib] | (1u << ib);
    int jb = __ffs(rem) - 1; rem &= rem - 1;

    // prologue: Q tile + first block's two 64-key tiles
    #pragma unroll
    for (int it = 0; it < 4; ++it) {
        int idx = tid + it * 256;
        int r = idx >> 4, ch = idx & 15;
        cpa16(sb + B_Q + r * LDQ + ch * 16, g_cn + (bC + r) * NPOS + m0 + ch * 8);
    }
    #pragma unroll
    for (int u = 0; u < 2; ++u) {
        const int n0 = jb * BM + u * 64;
        uint32_t base = sb + B_KV + u * KBUF;
        #pragma unroll
        for (int it = 0; it < 2; ++it) {
            int idx = tid + it * 256;
            int r = idx >> 3, ch = idx & 7;
            cpa16(base + r * LDKB + ch * 16, g_cn + (bC + r) * NPOS + n0 + ch * 8);
        }
    }
    CP_COMMIT();
    CP_WAIT0();
    __syncthreads();

    uint32_t QF[4][4];
    #pragma unroll
    for (int k = 0; k < 4; ++k) {
        uint32_t r0, r1, r2, r3;
        ldsm_x4t(sb + B_Q + (k * 16 + l16) * LDQ + w * 32 + hsel, r0, r1, r2, r3);
        QF[k][0] = r0; QF[k][1] = r2; QF[k][2] = r1; QF[k][3] = r3;
    }

    const int r0row = w * 16 + g;
    const float M0 = __int_as_float(g_M[bN + m0 + r0row]);
    const float M1 = __int_as_float(g_M[bN + m0 + r0row + 8]);
    const __half2 m0h = __float2half2_rn(M0);
    const __half2 m1h = __float2half2_rn(M1);
    const __half2 l2e = __float2half2_rn(L2E);

    float O[8][4], Ol[4];
    #pragma unroll
    for (int i = 0; i < 8; ++i)
        #pragma unroll
        for (int k = 0; k < 4; ++k) O[i][k] = 0.f;
    #pragma unroll
    for (int k = 0; k < 4; ++k) Ol[k] = 0.f;

    for (;;) {
        // process the two resident tiles
        #pragma unroll
        for (int u = 0; u < 2; ++u) {
            const uint32_t kvb = sb + B_KV + u * KBUF;

            uint32_t Sc0[8], Sc1[8];
            #pragma unroll
            for (int s = 0; s < 8; ++s) { Sc0[s] = 0u; Sc1[s] = 0u; }
            #pragma unroll
            for (int k = 0; k < 4; ++k) {
                const uint32_t krow = kvb + (k * 16 + l16) * LDKB + hsel;
                #pragma unroll
                for (int nt2 = 0; nt2 < 4; ++nt2) {
                    uint32_t b0, b1, b2, b3;
                    ldsm_x4t(krow + nt2 * 32, b0, b1, b2, b3);
                    mma16816h(Sc0[2 * nt2],     Sc1[2 * nt2],
                              QF[k][0], QF[k][1], QF[k][2], QF[k][3], b0, b1);
                    mma16816h(Sc0[2 * nt2 + 1], Sc1[2 * nt2 + 1],
                              QF[k][0], QF[k][1], QF[k][2], QF[k][3], b2, b3);
                }
            }

            uint32_t P01[8], P23[8];
            #pragma unroll
            for (int s = 0; s < 8; ++s) {
                P01[s] = ex2h2(h2u(__hmul2(__hsub2(u2h(Sc0[s]), m0h), l2e)));
                P23[s] = ex2h2(h2u(__hmul2(__hsub2(u2h(Sc1[s]), m1h), l2e)));
            }

            #pragma unroll
            for (int kk = 0; kk < 4; ++kk) {
                const uint32_t a0 = P01[2 * kk],     a1 = P23[2 * kk];
                const uint32_t a2 = P01[2 * kk + 1], a3 = P23[2 * kk + 1];
                #pragma unroll
                for (int ct2 = 0; ct2 < 4; ++ct2) {
                    uint32_t r0, r1, r2, r3;
                    ldsm_x4(kvb + (ct2 * 16 + l16) * LDKB + kk * 32 + hsel,
                            r0, r1, r2, r3);
                    mma16816(O[2 * ct2],     a0, a1, a2, a3, r0, r2);
                    mma16816(O[2 * ct2 + 1], a0, a1, a2, a3, r1, r3);
                }
                {
                    uint32_t o0, o1;
                    ldsm_x2(kvb + (64 + (l16 & 7)) * LDKB + kk * 32 +
                            ((l16 >> 3) * 16), o0, o1);
                    mma16816(Ol, a0, a1, a2, a3, o0, o1);
                }
            }
        }

        if (!rem) break;
        jb = __ffs(rem) - 1; rem &= rem - 1;
        __syncthreads();   // everyone done with buffers
        #pragma unroll
        for (int u = 0; u < 2; ++u) {
            const int n0 = jb * BM + u * 64;
            uint32_t base = sb + B_KV + u * KBUF;
            #pragma unroll
            for (int it = 0; it < 2; ++it) {
                int idx = tid + it * 256;
                int r = idx >> 3, ch = idx & 7;
                cpa16(base + r * LDKB + ch * 16, g_cn + (bC + r) * NPOS + n0 + ch * 8);
            }
        }
        CP_COMMIT();
        CP_WAIT0();
        __syncthreads();
    }

    __syncthreads();

    // ---- epilogue ----
    float* Sst = (float*)smraw;
    const float i0 = 1.0f / Ol[0], i1 = 1.0f / Ol[2];
    const int r1row = r0row + 8;
    #pragma unroll
    for (int ct = 0; ct < 8; ++ct) {
        Sst[r0row * LDO + 8 * ct + 2 * q]     = O[ct][0] * i0;
        Sst[r0row * LDO + 8 * ct + 2 * q + 1] = O[ct][1] * i0;
        Sst[r1row * LDO + 8 * ct + 2 * q]     = O[ct][2] * i1;
        Sst[r1row * LDO + 8 * ct + 2 * q + 1] = O[ct][3] * i1;
    }
    __syncthreads();

    #pragma unroll
    for (int it = 0; it < 32; ++it) {
        int flat = it * 256 + tid;
        int m = flat & 127, c = flat >> 7;
        const size_t o = (bC + c) * NPOS + m0 + m;
        out[o] = x[o] + Sst[m * LDO + c];
    }
}

extern "C" void kernel_launch(void* const* d_in, const int* in_sizes, int n_in,
                              void* d_out, int out_size)
{
    const float* x = (const float*)d_in[0];
    float* out = (float*)d_out;

    prep_kernel<<<(NB * C * NPOS) / 1024, 256>>>(x);
    diag_kernel<<<dim3(NPOS / 256, NB), 256>>>();

    cudaFuncSetAttribute(screen_kernel,
                         cudaFuncAttributeMaxDynamicSharedMemorySize, A_SMEM);
    screen_kernel<<<dim3(NPAIR, NB), 256, A_SMEM>>>();

    cudaFuncSetAttribute(attn_mma_kernel,
                         cudaFuncAttributeMaxDynamicSharedMemorySize, B_SMEM);
    attn_mma_kernel<<<dim3(NBLK, NB), 256, B_SMEM>>>(x, out);
}